// round 11
// baseline (speedup 1.0000x reference)
#include <cuda_runtime.h>
#include <math.h>

#define DD 256
#define BATCH 4
#define NN 512

typedef unsigned long long u64;

// Scratch: xp = x @ Wx  (B*N, D);  ypb = y @ Wy + b1  (B*N, D)
__device__ float g_xp[BATCH * NN * DD];
__device__ float g_ypb[BATCH * NN * DD];
__device__ int   g_flag[4];          // per-d-chunk GEMM completion counters

#define NPROD 256        // producer blocks (GEMM)
#define FLAG_TGT 256     // tiles per chunk (2 sel x 32 mtiles x 4 nquads)

// ---- f32x2 packed-math primitives (fma pipe, 2 fp32 per slot) -------------
#define F2FMA(D_, A_, B_, C_) \
    asm("fma.rn.f32x2 %0, %1, %2, %3;" : "=l"(D_) : "l"(A_), "l"(B_), "l"(C_))
#define F2ADD(D_, A_, B_) \
    asm("add.rn.f32x2 %0, %1, %2;" : "=l"(D_) : "l"(A_), "l"(B_))
#define F2MUL(D_, A_, B_) \
    asm("mul.rn.f32x2 %0, %1, %2;" : "=l"(D_) : "l"(A_), "l"(B_))
#define PK(D_, LO_, HI_) \
    asm("mov.b64 %0, {%1, %2};" : "=l"(D_) : "f"(LO_), "f"(HI_))
#define UNPK(LO_, HI_, S_) \
    asm("mov.b64 {%0, %1}, %2;" : "=f"(LO_), "=f"(HI_) : "l"(S_))

__device__ __forceinline__ float tanh_fast(float v) {
    float r;
    asm("tanh.approx.f32 %0, %1;" : "=f"(r) : "f"(v));
    return r;
}

#define GC0 0.79788456080286536f          // sqrt(2/pi)
#define GC1 0.03567740813636141f          // sqrt(2/pi)*0.044715

#define SX 34       // cross smem row stride
#define DCH 64      // d-chunk

// spin until GEMM chunk c is complete (deadlock-safe: producers are resident)
__device__ __forceinline__ void waitflag(int c) {
    if (threadIdx.x == 0 && threadIdx.y == 0) {
        while (((volatile int*)g_flag)[c] < FLAG_TGT) __nanosleep(128);
    }
    __syncthreads();
}

// ---------------------------------------------------------------------------
// Fused kernel. bid < NPROD: producer — GEMM output-column chunk pipeline.
//   producer p: sel=(p>>7)&1, mtile=(p>>2)&31, nquad=p&3; for c=0..3 computes
//   out[mtile*64 .. +64, c*64+nquad*16 .. +16], flags g_flag[c].
// bid >= NPROD: consumer — R10 cross tile, gated per chunk on g_flag.
// ---------------------------------------------------------------------------
__global__ __launch_bounds__(256, 4) void fused_kernel(
    const float* __restrict__ x,
    const float* __restrict__ y,
    const float* __restrict__ W1,
    const float* __restrict__ b1,
    const float* __restrict__ W2,
    const float* __restrict__ b2,
    float* __restrict__ out)
{
    extern __shared__ float sm[];
    const int tx = threadIdx.x;     // 0..15
    const int ty = threadIdx.y;     // 0..15
    const int t  = ty * 16 + tx;
    const int bid = blockIdx.x;

    if (bid < NPROD) {
        // ================= PRODUCER (GEMM) =================
        float (*As)[16][68] = (float (*)[16][68])sm;            // [2][16][68]
        float (*Bs)[16][20] = (float (*)[16][20])(sm + 2*16*68); // [2][16][20]

        const int p    = bid;
        const int nq   = p & 3;
        const int mt   = (p >> 2) & 31;
        const int sel  = (p >> 7) & 1;
        const float* X = sel ? y : x;
        const float* W = sel ? (W1 + 256 * 256) : W1;
        float* outg    = sel ? g_ypb : g_xp;
        const int m0   = mt * 64;

        const int fm = t >> 2;          // A row 0..63
        const int fk = (t & 3) * 4;     // A k quad
        const int gk = t >> 4;          // B k row 0..15
        const int gn = t & 15;          // B col (1 float)

        for (int c = 0; c < 4; ++c) {
            const int n0 = c * 64 + nq * 16;
            float acc[4] = {0.f, 0.f, 0.f, 0.f};

            // K prologue: chunk 0 -> stage 0
            float4 av = *(const float4*)&X[(m0 + fm) * 256 + fk];
            float  bw = W[gk * 256 + n0 + gn];
            As[0][fk + 0][fm] = av.x;
            As[0][fk + 1][fm] = av.y;
            As[0][fk + 2][fm] = av.z;
            As[0][fk + 3][fm] = av.w;
            Bs[0][gk][gn] = bw;
            __syncthreads();

            for (int kc = 0; kc < 16; ++kc) {
                const int s = kc & 1;
                if (kc < 15) {
                    const int k0 = (kc + 1) * 16;
                    av = *(const float4*)&X[(m0 + fm) * 256 + k0 + fk];
                    bw = W[(k0 + gk) * 256 + n0 + gn];
                }
                #pragma unroll
                for (int kk = 0; kk < 16; ++kk) {
                    float4 a = *(const float4*)&As[s][kk][ty * 4];
                    float  b = Bs[s][kk][tx];
                    acc[0] = fmaf(a.x, b, acc[0]);
                    acc[1] = fmaf(a.y, b, acc[1]);
                    acc[2] = fmaf(a.z, b, acc[2]);
                    acc[3] = fmaf(a.w, b, acc[3]);
                }
                if (kc < 15) {
                    const int s2 = s ^ 1;
                    As[s2][fk + 0][fm] = av.x;
                    As[s2][fk + 1][fm] = av.y;
                    As[s2][fk + 2][fm] = av.z;
                    As[s2][fk + 3][fm] = av.w;
                    Bs[s2][gk][gn] = bw;
                    __syncthreads();
                }
            }

            // epilogue: 4 rows, 1 col per thread
            const float bb1 = sel ? b1[n0 + tx] : 0.0f;
            #pragma unroll
            for (int i = 0; i < 4; ++i) {
                int m = m0 + ty * 4 + i;
                outg[m * 256 + n0 + tx] = acc[i] + bb1;
            }

            __threadfence();            // make this thread's stores visible
            __syncthreads();            // all threads' fences done; smem free
            if (t == 0) atomicAdd(&g_flag[c], 1);
        }
        return;
    }

    // ================= CONSUMER (cross) =================
    float* xs0 = sm;                     // [2][DCH*SX]
    float* ys0 = sm + 2 * DCH * SX;      // [2][DCH*SX]
    float* ws2 = sm + 4 * DCH * SX;      // [512]

    const int cid = bid - NPROD;
    const int bz = cid >> 8;
    const int n0 = ((cid >> 4) & 15) * 32;
    const int m0 = (cid & 15) * 32;

    const float* xp = g_xp  + (bz * NN + n0) * DD;
    const float* yp = g_ypb + (bz * NN + m0) * DD;

    {
        float wv = 0.5f * W2[t];
        u64 wp; PK(wp, wv, wv);
        *(u64*)&ws2[2 * t] = wp;
    }

    u64 C0P, C1P;
    PK(C0P, GC0, GC0);
    PK(C1P, GC1, GC1);

    u64 acc0 = 0ull, acc1 = 0ull;   // (a00,a01), (a10,a11)

    const int r  = t >> 3;    // 0..31
    const int cq = t & 7;     // 0..7

    float4 px[2], py[2];

    // prologue: wait chunk 0, LDG (L2-coherent), STS buffer 0
    waitflag(0);
    #pragma unroll
    for (int it = 0; it < 2; ++it) {
        int dg = 32 * it + 4 * cq;
        px[it] = __ldcg((const float4*)&xp[r * 256 + dg]);
        py[it] = __ldcg((const float4*)&yp[r * 256 + dg]);
    }
    #pragma unroll
    for (int it = 0; it < 2; ++it) {
        int dl = 32 * it + 4 * cq;
        xs0[(dl + 0) * SX + r] = px[it].x;
        xs0[(dl + 1) * SX + r] = px[it].y;
        xs0[(dl + 2) * SX + r] = px[it].z;
        xs0[(dl + 3) * SX + r] = px[it].w;
        ys0[(dl + 0) * SX + r] = py[it].x;
        ys0[(dl + 1) * SX + r] = py[it].y;
        ys0[(dl + 2) * SX + r] = py[it].z;
        ys0[(dl + 3) * SX + r] = py[it].w;
    }
    __syncthreads();

    #pragma unroll
    for (int c = 0; c < 4; ++c) {
        const int buf = c & 1;
        const float* xsb = xs0 + buf * DCH * SX;
        const float* ysb = ys0 + buf * DCH * SX;
        const float* xsp = xsb + 2 * ty;
        const float* ysp = ysb + 2 * tx;
        const float* wc  = ws2 + c * 2 * DCH;

        // wait + prefetch chunk c+1 (overlaps compute below)
        if (c < 3) {
            waitflag(c + 1);
            #pragma unroll
            for (int it = 0; it < 2; ++it) {
                int dg = (c + 1) * DCH + 32 * it + 4 * cq;
                px[it] = __ldcg((const float4*)&xp[r * 256 + dg]);
                py[it] = __ldcg((const float4*)&yp[r * 256 + dg]);
            }
        }

        #pragma unroll 8
        for (int d = 0; d < DCH; ++d) {
            float2 xv = *(const float2*)&xsp[d * SX];
            u64 Y = *(const u64*)&ysp[d * SX];
            u64 W = *(const u64*)&wc[2 * d];
            u64 X0, X1;
            PK(X0, xv.x, xv.x);
            PK(X1, xv.y, xv.y);

            #define GEL2(ACC, XB)                               \
            {                                                   \
                u64 H, Q, S, U, T, G;                           \
                float u0, u1, t0, t1;                           \
                F2ADD(H, XB, Y);                                \
                F2MUL(Q, H, H);                                 \
                F2FMA(S, Q, C1P, C0P);                          \
                F2MUL(U, H, S);                                 \
                UNPK(u0, u1, U);                                \
                t0 = tanh_fast(u0);                             \
                t1 = tanh_fast(u1);                             \
                PK(T, t0, t1);                                  \
                F2FMA(G, H, T, H);                              \
                F2FMA(ACC, G, W, ACC);                          \
            }

            GEL2(acc0, X0)
            GEL2(acc1, X1)
            #undef GEL2
        }

        if (c < 3) {
            float* xsn = xs0 + (buf ^ 1) * DCH * SX;
            float* ysn = ys0 + (buf ^ 1) * DCH * SX;
            #pragma unroll
            for (int it = 0; it < 2; ++it) {
                int dl = 32 * it + 4 * cq;
                xsn[(dl + 0) * SX + r] = px[it].x;
                xsn[(dl + 1) * SX + r] = px[it].y;
                xsn[(dl + 2) * SX + r] = px[it].z;
                xsn[(dl + 3) * SX + r] = px[it].w;
                ysn[(dl + 0) * SX + r] = py[it].x;
                ysn[(dl + 1) * SX + r] = py[it].y;
                ysn[(dl + 2) * SX + r] = py[it].z;
                ysn[(dl + 3) * SX + r] = py[it].w;
            }
            __syncthreads();
        }
    }

    const float bb = b2[0];
    u64 bpair; PK(bpair, bb, bb);
    F2ADD(acc0, acc0, bpair);
    F2ADD(acc1, acc1, bpair);

    const int n = n0 + 2 * ty;
    const int m = m0 + 2 * tx;
    float* orow = out + (size_t)(bz * NN + n) * NN + m;
    *(u64*)&orow[0]  = acc0;
    *(u64*)&orow[NN] = acc1;
}

// ---------------------------------------------------------------------------
extern "C" void kernel_launch(void* const* d_in, const int* in_sizes, int n_in,
                              void* d_out, int out_size)
{
    const float* x  = (const float*)d_in[0];
    const float* y  = (const float*)d_in[1];
    const float* W1 = (const float*)d_in[2];
    const float* b1 = (const float*)d_in[3];
    const float* W2 = (const float*)d_in[4];
    const float* b2 = (const float*)d_in[5];
    float* out = (float*)d_out;

    (void)in_sizes; (void)n_in; (void)out_size;

    // reset chunk flags (graph node; runs before the fused kernel each replay)
    void* flagp = nullptr;
    cudaGetSymbolAddress(&flagp, g_flag);
    cudaMemsetAsync(flagp, 0, 4 * sizeof(int));

    const int smem_bytes = (4 * DCH * SX + 512) * (int)sizeof(float);
    cudaFuncSetAttribute(fused_kernel,
                         cudaFuncAttributeMaxDynamicSharedMemorySize,
                         smem_bytes);

    dim3 blk(16, 16);
    fused_kernel<<<NPROD + 16 * 16 * BATCH, blk, smem_bytes>>>(
        x, y, W1, b1, W2, b2, out);
}

// round 12
// speedup vs baseline: 1.3454x; 1.3454x over previous
#include <cuda_runtime.h>
#include <math.h>

#define DD 256
#define BATCH 4
#define NN 512

typedef unsigned long long u64;

// Scratch: xp = x @ Wx  (B*N, D);  ypb = y @ Wy + b1  (B*N, D)
__device__ float g_xp[BATCH * NN * DD];
__device__ float g_ypb[BATCH * NN * DD];

// ---- f32x2 packed-math primitives (fma pipe, 2 fp32 per slot) -------------
#define F2FMA(D_, A_, B_, C_) \
    asm("fma.rn.f32x2 %0, %1, %2, %3;" : "=l"(D_) : "l"(A_), "l"(B_), "l"(C_))
#define F2ADD(D_, A_, B_) \
    asm("add.rn.f32x2 %0, %1, %2;" : "=l"(D_) : "l"(A_), "l"(B_))
#define F2MUL(D_, A_, B_) \
    asm("mul.rn.f32x2 %0, %1, %2;" : "=l"(D_) : "l"(A_), "l"(B_))
#define PK(D_, LO_, HI_) \
    asm("mov.b64 %0, {%1, %2};" : "=l"(D_) : "f"(LO_), "f"(HI_))
#define UNPK(LO_, HI_, S_) \
    asm("mov.b64 {%0, %1}, %2;" : "=f"(LO_), "=f"(HI_) : "l"(S_))

__device__ __forceinline__ float tanh_fast(float v) {
    float r;
    asm("tanh.approx.f32 %0, %1;" : "=f"(r) : "f"(v));
    return r;
}

#define GC0 0.79788456080286536f          // sqrt(2/pi)
#define GC1 0.03567740813636141f          // sqrt(2/pi)*0.044715

// ---------------------------------------------------------------------------
// Merged GEMM: z=0: g_xp = x @ W1[0:256];  z=1: g_ypb = y @ W1[256:512] + b1
// R9 structure (64x64 tiles, BK=16, 256 threads, 4x4 micro-tile, double-
// buffered smem + register prefetch, 1 sync/chunk). Inner loop upgraded to
// f32x2: A via LDS.128 + register (a,a) packs (alu pipe), B via 2x LDS.64.
// ---------------------------------------------------------------------------
__global__ __launch_bounds__(256) void gemm_kernel(
    const float* __restrict__ x,
    const float* __restrict__ y,
    const float* __restrict__ W1,
    const float* __restrict__ b1)
{
    __shared__ float As[2][16][68];   // [stage][k][m] (A transposed)
    __shared__ float Bs[2][16][68];   // [stage][k][n]

    const int sel = blockIdx.z;
    const float* X = sel ? y : x;
    const float* W = sel ? (W1 + 256 * 256) : W1;
    float* out = sel ? g_ypb : g_xp;

    const int tx = threadIdx.x;     // 0..15
    const int ty = threadIdx.y;     // 0..15
    const int t  = ty * 16 + tx;
    const int m0 = blockIdx.y * 64;
    const int n0 = blockIdx.x * 64;

    // fill roles
    const int fm = t >> 2;          // A row 0..63
    const int fk = (t & 3) * 4;     // A k quad
    const int gk = t >> 4;          // B k row 0..15
    const int gn = (t & 15) * 4;    // B col quad

    u64 acc[4][2];
    #pragma unroll
    for (int i = 0; i < 4; ++i) { acc[i][0] = 0ull; acc[i][1] = 0ull; }

    // prologue: chunk 0 -> stage 0
    float4 av = *(const float4*)&X[(m0 + fm) * 256 + fk];
    float4 bv = *(const float4*)&W[gk * 256 + n0 + gn];
    As[0][fk + 0][fm] = av.x;
    As[0][fk + 1][fm] = av.y;
    As[0][fk + 2][fm] = av.z;
    As[0][fk + 3][fm] = av.w;
    *(float4*)&Bs[0][gk][gn] = bv;
    __syncthreads();

    for (int kc = 0; kc < 16; ++kc) {
        const int s = kc & 1;
        if (kc < 15) {
            const int k0 = (kc + 1) * 16;
            av = *(const float4*)&X[(m0 + fm) * 256 + k0 + fk];
            bv = *(const float4*)&W[(k0 + gk) * 256 + n0 + gn];
        }

        #pragma unroll
        for (int kk = 0; kk < 16; ++kk) {
            float4 a = *(const float4*)&As[s][kk][ty * 4];   // LDS.128
            u64 B0 = *(const u64*)&Bs[s][kk][tx * 4];        // LDS.64
            u64 B1 = *(const u64*)&Bs[s][kk][tx * 4 + 2];    // LDS.64
            u64 A0, A1, A2, A3;
            PK(A0, a.x, a.x);
            PK(A1, a.y, a.y);
            PK(A2, a.z, a.z);
            PK(A3, a.w, a.w);
            F2FMA(acc[0][0], A0, B0, acc[0][0]);
            F2FMA(acc[0][1], A0, B1, acc[0][1]);
            F2FMA(acc[1][0], A1, B0, acc[1][0]);
            F2FMA(acc[1][1], A1, B1, acc[1][1]);
            F2FMA(acc[2][0], A2, B0, acc[2][0]);
            F2FMA(acc[2][1], A2, B1, acc[2][1]);
            F2FMA(acc[3][0], A3, B0, acc[3][0]);
            F2FMA(acc[3][1], A3, B1, acc[3][1]);
        }

        if (kc < 15) {
            const int s2 = s ^ 1;
            As[s2][fk + 0][fm] = av.x;
            As[s2][fk + 1][fm] = av.y;
            As[s2][fk + 2][fm] = av.z;
            As[s2][fk + 3][fm] = av.w;
            *(float4*)&Bs[s2][gk][gn] = bv;
            __syncthreads();
        }
    }

    #pragma unroll
    for (int i = 0; i < 4; ++i) {
        int m = m0 + ty * 4 + i;
        int n = n0 + tx * 4;
        float c0, c1, c2, c3;
        UNPK(c0, c1, acc[i][0]);
        UNPK(c2, c3, acc[i][1]);
        if (sel) {
            c0 += b1[n + 0]; c1 += b1[n + 1];
            c2 += b1[n + 2]; c3 += b1[n + 3];
        }
        float4 o = {c0, c1, c2, c3};
        *(float4*)&out[m * 256 + n] = o;
    }
}

// ---------------------------------------------------------------------------
// Cross kernel (R10 form, FROZEN): block = (b, 32n x 32m) tile; thread = 2x2
// micro-tile as two f32x2 groups. d chunked 4x64, double-buffered smem +
// register prefetch, one sync per chunk.
// ---------------------------------------------------------------------------
#define SX 34       // row stride (floats): even for LDS.64 align, conflict-free
#define DCH 64      // d-chunk (4 chunks of 64)

__global__ __launch_bounds__(256, 4) void cross_kernel(
    const float* __restrict__ W2,
    const float* __restrict__ b2,
    float* __restrict__ out)
{
    extern __shared__ float sm[];
    float* xs0 = sm;                     // [2][DCH*SX]
    float* ys0 = sm + 2 * DCH * SX;      // [2][DCH*SX]
    float* ws2 = sm + 4 * DCH * SX;      // [512]

    const int tx = threadIdx.x;        // 0..15 -> m
    const int ty = threadIdx.y;        // 0..15 -> n
    const int t  = ty * 16 + tx;
    const int bz = blockIdx.z;
    const int n0 = blockIdx.y * 32;
    const int m0 = blockIdx.x * 32;

    const float* xp = g_xp  + (bz * NN + n0) * DD;
    const float* yp = g_ypb + (bz * NN + m0) * DD;

    // ws2 once (all 256 d)
    {
        float wv = 0.5f * W2[t];
        u64 wp; PK(wp, wv, wv);
        *(u64*)&ws2[2 * t] = wp;
    }

    u64 C0P, C1P;
    PK(C0P, GC0, GC0);
    PK(C1P, GC1, GC1);

    u64 acc0 = 0ull, acc1 = 0ull;   // (a00,a01), (a10,a11)

    const int r  = t >> 3;    // 0..31
    const int cq = t & 7;     // 0..7

    float4 px[2], py[2];

    // prologue: LDG chunk 0, STS to buffer 0
    #pragma unroll
    for (int it = 0; it < 2; ++it) {
        int dg = 32 * it + 4 * cq;
        px[it] = *(const float4*)&xp[r * 256 + dg];
        py[it] = *(const float4*)&yp[r * 256 + dg];
    }
    #pragma unroll
    for (int it = 0; it < 2; ++it) {
        int dl = 32 * it + 4 * cq;
        xs0[(dl + 0) * SX + r] = px[it].x;
        xs0[(dl + 1) * SX + r] = px[it].y;
        xs0[(dl + 2) * SX + r] = px[it].z;
        xs0[(dl + 3) * SX + r] = px[it].w;
        ys0[(dl + 0) * SX + r] = py[it].x;
        ys0[(dl + 1) * SX + r] = py[it].y;
        ys0[(dl + 2) * SX + r] = py[it].z;
        ys0[(dl + 3) * SX + r] = py[it].w;
    }
    __syncthreads();

    #pragma unroll
    for (int c = 0; c < 4; ++c) {
        const int buf = c & 1;
        const float* xsb = xs0 + buf * DCH * SX;
        const float* ysb = ys0 + buf * DCH * SX;
        const float* xsp = xsb + 2 * ty;
        const float* ysp = ysb + 2 * tx;
        const float* wc  = ws2 + c * 2 * DCH;

        // prefetch chunk c+1 (overlaps compute below)
        if (c < 3) {
            #pragma unroll
            for (int it = 0; it < 2; ++it) {
                int dg = (c + 1) * DCH + 32 * it + 4 * cq;
                px[it] = *(const float4*)&xp[r * 256 + dg];
                py[it] = *(const float4*)&yp[r * 256 + dg];
            }
        }

        #pragma unroll 8
        for (int d = 0; d < DCH; ++d) {
            float2 xv = *(const float2*)&xsp[d * SX];
            u64 Y = *(const u64*)&ysp[d * SX];
            u64 W = *(const u64*)&wc[2 * d];
            u64 X0, X1;
            PK(X0, xv.x, xv.x);
            PK(X1, xv.y, xv.y);

            #define GEL2(ACC, XB)                               \
            {                                                   \
                u64 H, Q, S, U, T, G;                           \
                float u0, u1, t0, t1;                           \
                F2ADD(H, XB, Y);                                \
                F2MUL(Q, H, H);                                 \
                F2FMA(S, Q, C1P, C0P);                          \
                F2MUL(U, H, S);                                 \
                UNPK(u0, u1, U);                                \
                t0 = tanh_fast(u0);                             \
                t1 = tanh_fast(u1);                             \
                PK(T, t0, t1);                                  \
                F2FMA(G, H, T, H);                              \
                F2FMA(ACC, G, W, ACC);                          \
            }

            GEL2(acc0, X0)
            GEL2(acc1, X1)
            #undef GEL2
        }

        // store chunk c+1 into the other buffer, then sync
        if (c < 3) {
            float* xsn = xs0 + (buf ^ 1) * DCH * SX;
            float* ysn = ys0 + (buf ^ 1) * DCH * SX;
            #pragma unroll
            for (int it = 0; it < 2; ++it) {
                int dl = 32 * it + 4 * cq;
                xsn[(dl + 0) * SX + r] = px[it].x;
                xsn[(dl + 1) * SX + r] = px[it].y;
                xsn[(dl + 2) * SX + r] = px[it].z;
                xsn[(dl + 3) * SX + r] = px[it].w;
                ysn[(dl + 0) * SX + r] = py[it].x;
                ysn[(dl + 1) * SX + r] = py[it].y;
                ysn[(dl + 2) * SX + r] = py[it].z;
                ysn[(dl + 3) * SX + r] = py[it].w;
            }
            __syncthreads();
        }
    }

    const float bb = b2[0];
    u64 bpair; PK(bpair, bb, bb);
    F2ADD(acc0, acc0, bpair);
    F2ADD(acc1, acc1, bpair);

    const int n = n0 + 2 * ty;
    const int m = m0 + 2 * tx;
    float* orow = out + (size_t)(bz * NN + n) * NN + m;
    *(u64*)&orow[0]  = acc0;
    *(u64*)&orow[NN] = acc1;
}

// ---------------------------------------------------------------------------
extern "C" void kernel_launch(void* const* d_in, const int* in_sizes, int n_in,
                              void* d_out, int out_size)
{
    const float* x  = (const float*)d_in[0];
    const float* y  = (const float*)d_in[1];
    const float* W1 = (const float*)d_in[2];
    const float* b1 = (const float*)d_in[3];
    const float* W2 = (const float*)d_in[4];
    const float* b2 = (const float*)d_in[5];
    float* out = (float*)d_out;

    (void)in_sizes; (void)n_in; (void)out_size;

    const int smem_cross = (4 * DCH * SX + 512) * (int)sizeof(float);
    cudaFuncSetAttribute(cross_kernel,
                         cudaFuncAttributeMaxDynamicSharedMemorySize,
                         smem_cross);

    dim3 gblk(16, 16);      // 256 threads
    dim3 ggrid(4, 32, 2);   // 256 blocks, both GEMMs in one launch
    gemm_kernel<<<ggrid, gblk>>>(x, y, W1, b1);

    dim3 cblk(16, 16);
    dim3 cgrid(16, 16, 4);  // (m-tiles, n-tiles, batch)
    cross_kernel<<<cgrid, cblk, smem_cross>>>(W2, b2, out);
}